// round 6
// baseline (speedup 1.0000x reference)
#include <cuda_runtime.h>
#include <math.h>

// QuantumLayer: 4-qubit circuit, closed-form with phase folding.
//   z_q = R_q * cos(x_q - delta_q)
//   out0 = C0*c1c2c3, out1 = C1*c0c1, out2 = C2*c0c1c2, out3 = C3*c0c1c2c3
// Output layout: [NQ, B] float32, B = 1<<20 exactly (512 * 256 * 8).
//
// SAMP=8 per thread: 8 front-batched coalesced LDG.128 (MLP=8), then
// compute+store streamed per sample to bound register pressure.

#define SAMP 8
#define TPB  256

__global__ __launch_bounds__(TPB)
void quantum_layer_kernel(const float* __restrict__ x,
                          const float* __restrict__ w,
                          float* __restrict__ out,
                          int B) {
    __shared__ float sD[4];   // delta_q
    __shared__ float sR[4];   // R_q
    if (threadIdx.x < 4) {
        int q = threadIdx.x;
        float phi   = w[q * 3 + 0];
        float theta = w[q * 3 + 1];
        float st, ct;
        __sincosf(theta, &st, &ct);
        float kc = ct;
        float ks = -__cosf(phi) * st;
        sR[q] = sqrtf(kc * kc + ks * ks);
        sD[q] = atan2f(ks, kc);
    }
    __syncthreads();

    const float d0 = sD[0], d1 = sD[1], d2 = sD[2], d3 = sD[3];
    const float R0 = sR[0], R1 = sR[1], R2 = sR[2], R3 = sR[3];
    const float C1 = R0 * R1;
    const float C2 = C1 * R2;
    const float C3 = C2 * R3;
    const float C0 = R1 * R2 * R3;

    const unsigned i0 = blockIdx.x * (TPB * SAMP) + threadIdx.x;

    const float4* __restrict__ xin = reinterpret_cast<const float4*>(x) + i0;

    // Front-batched, unpredicated, coalesced loads (lane stride 16B, 4 lines/LDG).
    float4 xv[SAMP];
#pragma unroll
    for (int j = 0; j < SAMP; ++j) xv[j] = xin[j * TPB];

    float* __restrict__ o0 = out + i0;
    float* __restrict__ o1 = o0 + (unsigned)B;
    float* __restrict__ o2 = o1 + (unsigned)B;
    float* __restrict__ o3 = o2 + (unsigned)B;

#pragma unroll
    for (int j = 0; j < SAMP; ++j) {
        float c0 = __cosf(xv[j].x - d0);
        float c1 = __cosf(xv[j].y - d1);
        float c2 = __cosf(xv[j].z - d2);
        float c3 = __cosf(xv[j].w - d3);

        float a = c0 * c1;
        float b = c2 * c3;

        // Streamed stores: lane stride 4B -> 1 line per STG.32 warp instruction.
        o0[j * TPB] = C0 * (c1 * b);   // z1 z2 z3
        o1[j * TPB] = C1 * a;          // z0 z1
        o2[j * TPB] = C2 * (a * c2);   // z0 z1 z2
        o3[j * TPB] = C3 * (a * b);    // z0 z1 z2 z3
    }
}

extern "C" void kernel_launch(void* const* d_in, const int* in_sizes, int n_in,
                              void* d_out, int out_size) {
    const float* x = (const float*)d_in[0];   // inputs  [B, 4] float32
    const float* w = (const float*)d_in[1];   // weights [1, 4, 3] float32
    float* out = (float*)d_out;               // [4, B] float32

    int B = in_sizes[0] / 4;                  // 1<<20
    int samplesPerBlock = TPB * SAMP;         // 2048
    int blocks = (B + samplesPerBlock - 1) / samplesPerBlock;   // 512

    quantum_layer_kernel<<<blocks, TPB>>>(x, w, out, B);
}

// round 7
// speedup vs baseline: 1.0627x; 1.0627x over previous
#include <cuda_runtime.h>
#include <math.h>

// QuantumLayer: 4-qubit circuit, closed-form with phase folding.
//   z_q = R_q * cos(x_q - delta_q)
//   out0 = C0*c1c2c3, out1 = C1*c0c1, out2 = C2*c0c1c2, out3 = C3*c0c1c2c3
// Output layout: [NQ, B] float32, B = 1<<20.
//
// Grid = 592 = 4 * 148 CTAs of 256 threads: every SM gets exactly 4 CTAs
// (32 warps, the occupancy cap) -> perfect per-SM load balance, single wave.
// Each thread handles up to 7 samples at stride GRID*TPB; samples 0..5 are
// provably in-bounds (unpredicated), only the 7th is guarded.

#define TPB   256
#define GRID  592                       // 4 * 148
#define STRIDE (GRID * TPB)             // 151552
#define FULL_ITERS 6                    // i0 + 5*STRIDE < 2^20 always

__global__ __launch_bounds__(TPB)
void quantum_layer_kernel(const float* __restrict__ x,
                          const float* __restrict__ w,
                          float* __restrict__ out,
                          int B) {
    __shared__ float sD[4];   // delta_q
    __shared__ float sR[4];   // R_q
    if (threadIdx.x < 4) {
        int q = threadIdx.x;
        float phi   = w[q * 3 + 0];
        float theta = w[q * 3 + 1];
        float st, ct;
        __sincosf(theta, &st, &ct);
        float kc = ct;
        float ks = -__cosf(phi) * st;
        sR[q] = sqrtf(kc * kc + ks * ks);
        sD[q] = atan2f(ks, kc);
    }
    __syncthreads();

    const float d0 = sD[0], d1 = sD[1], d2 = sD[2], d3 = sD[3];
    const float R0 = sR[0], R1 = sR[1], R2 = sR[2], R3 = sR[3];
    const float C1 = R0 * R1;
    const float C2 = C1 * R2;
    const float C3 = C2 * R3;
    const float C0 = R1 * R2 * R3;

    const unsigned i0 = blockIdx.x * TPB + threadIdx.x;   // 0 .. STRIDE-1

    const float4* __restrict__ xv4 = reinterpret_cast<const float4*>(x);
    float* __restrict__ o0 = out;
    float* __restrict__ o1 = out + (unsigned)B;
    float* __restrict__ o2 = out + 2u * (unsigned)B;
    float* __restrict__ o3 = out + 3u * (unsigned)B;

    // ---- 6 unconditional samples, loads front-batched (MLP=6..7) ----
    float4 xv[FULL_ITERS];
#pragma unroll
    for (int j = 0; j < FULL_ITERS; ++j)
        xv[j] = xv4[i0 + (unsigned)j * STRIDE];

    // 7th (tail) sample, predicated load.
    const unsigned i6 = i0 + 6u * STRIDE;
    const bool has7 = (i6 < (unsigned)B);
    float4 xv6;
    if (has7) xv6 = xv4[i6];

#pragma unroll
    for (int j = 0; j < FULL_ITERS; ++j) {
        unsigned i = i0 + (unsigned)j * STRIDE;
        float c0 = __cosf(xv[j].x - d0);
        float c1 = __cosf(xv[j].y - d1);
        float c2 = __cosf(xv[j].z - d2);
        float c3 = __cosf(xv[j].w - d3);
        float a = c0 * c1;
        float b = c2 * c3;
        o0[i] = C0 * (c1 * b);
        o1[i] = C1 * a;
        o2[i] = C2 * (a * c2);
        o3[i] = C3 * (a * b);
    }

    if (has7) {
        float c0 = __cosf(xv6.x - d0);
        float c1 = __cosf(xv6.y - d1);
        float c2 = __cosf(xv6.z - d2);
        float c3 = __cosf(xv6.w - d3);
        float a = c0 * c1;
        float b = c2 * c3;
        o0[i6] = C0 * (c1 * b);
        o1[i6] = C1 * a;
        o2[i6] = C2 * (a * c2);
        o3[i6] = C3 * (a * b);
    }
}

extern "C" void kernel_launch(void* const* d_in, const int* in_sizes, int n_in,
                              void* d_out, int out_size) {
    const float* x = (const float*)d_in[0];   // inputs  [B, 4] float32
    const float* w = (const float*)d_in[1];   // weights [1, 4, 3] float32
    float* out = (float*)d_out;               // [4, B] float32

    int B = in_sizes[0] / 4;                  // 1<<20
    quantum_layer_kernel<<<GRID, TPB>>>(x, w, out, B);
}